// round 10
// baseline (speedup 1.0000x reference)
#include <cuda_runtime.h>
#include <cuda_fp16.h>
#include <cstdint>

#define M_TOTAL 16384
#define N_TOTAL 4096
#define K_TOTAL 4096
#define NSLOT   8

#define BM 128
#define BN 128
#define BK 64
#define STAGES 3
#define PADH 8
#define TSH (BK + PADH)       // 72 halves per smem row
#define ROWB (TSH * 2)        // 144 bytes per smem row

// Scratch (allocation-free rule: __device__ globals)
__device__ __half g_W[(size_t)N_TOTAL * K_TOTAL];
__device__ __half g_X[(size_t)M_TOTAL * K_TOTAL];
__device__ float  g_b[N_TOTAL];

// ---------------------------------------------------------------------------
// Kernel 1: W = fp16(weight + sum_i (scale_i*wscale_i)*wq_i + (scale . wzp))
// ---------------------------------------------------------------------------
__global__ void compute_w_kernel(const float* __restrict__ weight,
                                 const int*   __restrict__ wq,
                                 const float* __restrict__ scale,
                                 const float* __restrict__ wscale,
                                 const int*   __restrict__ wzp) {
    const size_t nvec = (size_t)N_TOTAL * K_TOTAL / 4;
    size_t idx = (size_t)blockIdx.x * blockDim.x + threadIdx.x;
    if (idx >= nvec) return;

    float c[NSLOT];
    float z = 0.f;
#pragma unroll
    for (int i = 0; i < NSLOT; i++) {
        float s = scale[i];
        c[i] = s * wscale[i];
        z += s * (float)wzp[i];
    }
    float4 w = reinterpret_cast<const float4*>(weight)[idx];
    float ax = w.x + z, ay = w.y + z, az = w.z + z, aw = w.w + z;
#pragma unroll
    for (int i = 0; i < NSLOT; i++) {
        int4 q = reinterpret_cast<const int4*>(wq)[(size_t)i * nvec + idx];
        ax += c[i] * (float)q.x;
        ay += c[i] * (float)q.y;
        az += c[i] * (float)q.z;
        aw += c[i] * (float)q.w;
    }
    __half2 lo = __floats2half2_rn(ax, ay);
    __half2 hi = __floats2half2_rn(az, aw);
    reinterpret_cast<uint2*>(g_W)[idx] =
        make_uint2(*reinterpret_cast<uint32_t*>(&lo), *reinterpret_cast<uint32_t*>(&hi));
}

// ---------------------------------------------------------------------------
// Kernel 1b: X -> fp16
// ---------------------------------------------------------------------------
__global__ void round_x_kernel(const float* __restrict__ x) {
    const size_t nvec = (size_t)M_TOTAL * K_TOTAL / 4;
    size_t idx = (size_t)blockIdx.x * blockDim.x + threadIdx.x;
    if (idx >= nvec) return;
    float4 v = reinterpret_cast<const float4*>(x)[idx];
    __half2 lo = __floats2half2_rn(v.x, v.y);
    __half2 hi = __floats2half2_rn(v.z, v.w);
    reinterpret_cast<uint2*>(g_X)[idx] =
        make_uint2(*reinterpret_cast<uint32_t*>(&lo), *reinterpret_cast<uint32_t*>(&hi));
}

// ---------------------------------------------------------------------------
// Kernel 2: b = bias + sum_i scale_i*(bscale_i*bq_i + bzp_i)
// ---------------------------------------------------------------------------
__global__ void compute_b_kernel(const float* __restrict__ bias,
                                 const float* __restrict__ scale,
                                 const int*   __restrict__ bq,
                                 const float* __restrict__ bscale,
                                 const int*   __restrict__ bzp) {
    int j = blockIdx.x * blockDim.x + threadIdx.x;
    if (j >= N_TOTAL) return;
    float acc = bias[j];
#pragma unroll
    for (int i = 0; i < NSLOT; i++)
        acc += scale[i] * (bscale[i] * (float)bq[i * N_TOTAL + j] + (float)bzp[i]);
    g_b[j] = acc;
}

// ---------------------------------------------------------------------------
// Kernel 3: fp16 m16n8k16 GEMM, ldmatrix, 8 warps (2x4), warp tile 64x32,
// half-granularity software-pipelined fragments, 3-stage cp.async,
// 2 CTAs/SM => 4 warps/SMSP.
// ---------------------------------------------------------------------------
extern __shared__ __half smem_h[];

__global__ void __launch_bounds__(256, 2)
gemm_fp16_kernel(float* __restrict__ OUT) {
    const int tid  = threadIdx.x;
    const int warp = tid >> 5;
    const int lane = tid & 31;
    const int wm = warp >> 2;   // 0..1 : 64 rows
    const int wn = warp & 3;    // 0..3 : 32 cols
    const int bm = blockIdx.y * BM;
    const int bn = blockIdx.x * BN;

    __half* As = smem_h;
    __half* Bs = smem_h + STAGES * BM * TSH;

    const uint32_t As_u = (uint32_t)__cvta_generic_to_shared(As);
    const uint32_t Bs_u = (uint32_t)__cvta_generic_to_shared(Bs);

    // producers: 256 threads, each owns half a row's k-tile data (64B)
    const int prow = tid >> 1;
    const int pcol = (tid & 1) * 32;
    const __half* a_src0 = g_X + (size_t)(bm + prow) * K_TOTAL + pcol;
    const __half* b_src0 = g_W + (size_t)(bn + prow) * K_TOTAL + pcol;
    const uint32_t pdst = prow * ROWB + (tid & 1) * 64;

    auto issue_tile = [&](int t) {
        const int s = t % STAGES;
        const int kofs = t * BK;
        uint32_t a_dst = As_u + s * BM * ROWB + pdst;
        uint32_t b_dst = Bs_u + s * BN * ROWB + pdst;
        const __half* a_src = a_src0 + kofs;
        const __half* b_src = b_src0 + kofs;
#pragma unroll
        for (int p = 0; p < 4; p++)
            asm volatile("cp.async.cg.shared.global [%0], [%1], 16;\n"
                         :: "r"(a_dst + p * 16), "l"(a_src + p * 8));
#pragma unroll
        for (int p = 0; p < 4; p++)
            asm volatile("cp.async.cg.shared.global [%0], [%1], 16;\n"
                         :: "r"(b_dst + p * 16), "l"(b_src + p * 8));
    };

    float acc[4][4][4];
#pragma unroll
    for (int mt = 0; mt < 4; mt++)
#pragma unroll
        for (int nt = 0; nt < 4; nt++)
#pragma unroll
            for (int r = 0; r < 4; r++) acc[mt][nt][r] = 0.f;

    const int KT = K_TOTAL / BK;   // 64

#pragma unroll
    for (int t = 0; t < STAGES - 1; t++) {
        issue_tile(t);
        asm volatile("cp.async.commit_group;\n");
    }

    // ldmatrix per-lane base offsets (bytes within a stage)
    const uint32_t a_lm = (uint32_t)((wm * 64 + (lane & 15)) * ROWB + (lane >> 4) * 16);
    const uint32_t b_lm = (uint32_t)((wn * 32 + ((lane >> 4) * 8 + (lane & 7))) * ROWB
                                     + ((lane >> 3) & 1) * 16);

    const int q = lane >> 2;
    const int c = lane & 3;

    // Fragment buffers: A split in halves (mt01 / mt23), B double-buffered.
    uint32_t afr[2][2][4];   // [half-buffer][j][frag]
    uint32_t bfr[2][4][2];   // [ks parity][nt][frag]

    for (int t = 0; t < KT; t++) {
        asm volatile("cp.async.wait_group %0;\n" :: "n"(STAGES - 2));
        __syncthreads();

        if (t + STAGES - 1 < KT) issue_tile(t + STAGES - 1);
        asm volatile("cp.async.commit_group;\n");

        const int s = t % STAGES;
        const uint32_t aS = As_u + s * BM * ROWB + a_lm;
        const uint32_t bS = Bs_u + s * BN * ROWB + b_lm;

        auto loadA = [&](int ks, int half, int buf) {
            const uint32_t kb = (uint32_t)ks * 32;
#pragma unroll
            for (int j = 0; j < 2; j++) {
                const int mt = half * 2 + j;
                asm volatile(
                    "ldmatrix.sync.aligned.m8n8.x4.shared.b16 {%0,%1,%2,%3}, [%4];"
                    : "=r"(afr[buf][j][0]), "=r"(afr[buf][j][1]),
                      "=r"(afr[buf][j][2]), "=r"(afr[buf][j][3])
                    : "r"(aS + mt * 16 * ROWB + kb));
            }
        };
        auto loadB = [&](int ks, int buf) {
            const uint32_t kb = (uint32_t)ks * 32;
#pragma unroll
            for (int pr = 0; pr < 2; pr++) {
                asm volatile(
                    "ldmatrix.sync.aligned.m8n8.x4.shared.b16 {%0,%1,%2,%3}, [%4];"
                    : "=r"(bfr[buf][2 * pr][0]), "=r"(bfr[buf][2 * pr][1]),
                      "=r"(bfr[buf][2 * pr + 1][0]), "=r"(bfr[buf][2 * pr + 1][1])
                    : "r"(bS + pr * 16 * ROWB + kb));
            }
        };
        auto mma_half = [&](int half, int abuf, int bbuf) {
#pragma unroll
            for (int j = 0; j < 2; j++) {
                const int mt = half * 2 + j;
#pragma unroll
                for (int nt = 0; nt < 4; nt++) {
                    asm volatile(
                        "mma.sync.aligned.m16n8k16.row.col.f32.f16.f16.f32 "
                        "{%0,%1,%2,%3}, {%4,%5,%6,%7}, {%8,%9}, {%0,%1,%2,%3};\n"
                        : "+f"(acc[mt][nt][0]), "+f"(acc[mt][nt][1]),
                          "+f"(acc[mt][nt][2]), "+f"(acc[mt][nt][3])
                        : "r"(afr[abuf][j][0]), "r"(afr[abuf][j][1]),
                          "r"(afr[abuf][j][2]), "r"(afr[abuf][j][3]),
                          "r"(bfr[bbuf][nt][0]), "r"(bfr[bbuf][nt][1]));
                }
            }
        };

        // prologue of the ks pipeline
        loadB(0, 0);
        loadA(0, 0, 0);   // mt01 of ks=0

#pragma unroll
        for (int ks = 0; ks < 4; ks++) {
            loadA(ks, 1, 1);                    // mt23 of current ks
            if (ks < 3) loadB(ks + 1, (ks + 1) & 1);
            mma_half(0, 0, ks & 1);             // HMMA mt01 (afr buf 0)
            if (ks < 3) loadA(ks + 1, 0, 0);    // mt01 of next ks
            mma_half(1, 1, ks & 1);             // HMMA mt23 (afr buf 1)
        }
        __syncthreads();
    }

    // epilogue: bias + store (C fragment layout of m16n8)
#pragma unroll
    for (int mt = 0; mt < 4; mt++) {
        const int row0 = bm + wm * 64 + mt * 16 + q;
#pragma unroll
        for (int nt = 0; nt < 4; nt++) {
            const int col = bn + wn * 32 + nt * 8 + c * 2;
            const float b0 = g_b[col];
            const float b1 = g_b[col + 1];
            float2 v0 = make_float2(acc[mt][nt][0] + b0, acc[mt][nt][1] + b1);
            float2 v1 = make_float2(acc[mt][nt][2] + b0, acc[mt][nt][3] + b1);
            *reinterpret_cast<float2*>(OUT + (size_t)row0 * N_TOTAL + col) = v0;
            *reinterpret_cast<float2*>(OUT + (size_t)(row0 + 8) * N_TOTAL + col) = v1;
        }
    }
}

// ---------------------------------------------------------------------------
extern "C" void kernel_launch(void* const* d_in, const int* in_sizes, int n_in,
                              void* d_out, int out_size) {
    const float* x      = (const float*)d_in[0];
    const float* weight = (const float*)d_in[1];
    const float* bias   = (const float*)d_in[2];
    const float* scale  = (const float*)d_in[3];
    const int*   wq     = (const int*)  d_in[4];
    const float* wscale = (const float*)d_in[5];
    const int*   wzp    = (const int*)  d_in[6];
    const int*   bq     = (const int*)  d_in[7];
    const float* bscale = (const float*)d_in[8];
    const int*   bzp    = (const int*)  d_in[9];
    float* out = (float*)d_out;

    {
        const size_t nvec = (size_t)N_TOTAL * K_TOTAL / 4;
        compute_w_kernel<<<(int)((nvec + 255) / 256), 256>>>(weight, wq, scale, wscale, wzp);
    }
    {
        const size_t nvec = (size_t)M_TOTAL * K_TOTAL / 4;
        round_x_kernel<<<(int)((nvec + 255) / 256), 256>>>(x);
    }
    compute_b_kernel<<<(N_TOTAL + 255) / 256, 256>>>(bias, scale, bq, bscale, bzp);

    {
        int smem_bytes = STAGES * (BM + BN) * TSH * (int)sizeof(__half);  // 110592
        cudaFuncSetAttribute(gemm_fp16_kernel,
                             cudaFuncAttributeMaxDynamicSharedMemorySize, smem_bytes);
        dim3 grid(N_TOTAL / BN, M_TOTAL / BM);   // (32, 128)
        gemm_fp16_kernel<<<grid, 256, smem_bytes>>>(out);
    }
}